// round 1
// baseline (speedup 1.0000x reference)
#include <cuda_runtime.h>
#include <math.h>

#define N_IMG 16
#define A 360
#define R 360
#define H 256
#define W 256
#define RW 12                    // 360 bits -> 12 x 32-bit words per angle
#define PIX_PER_BLOCK 2048
#define DELTA_RHO_D (2.0 * 181.01933598375618 / 359.0)   // 2*sqrt(128^2+128^2)/359

__device__ unsigned int g_max_bits[N_IMG];
__device__ unsigned int g_peak[N_IMG * A * RW];

// ---------------------------------------------------------------- init
__global__ void dm_init_kernel() {
    if (threadIdx.x < N_IMG) g_max_bits[threadIdx.x] = 0u;
}

// ---------------------------------------------------------------- per-image max
__global__ void dm_max_kernel(const float* __restrict__ in) {
    const int n = blockIdx.y;
    const float* img = in + (size_t)n * (A * R);
    int tid = blockIdx.x * blockDim.x + threadIdx.x;
    int stride = gridDim.x * blockDim.x;
    float m = 0.0f;   // input is uniform[0,1): non-negative
    for (int i = tid; i < A * R; i += stride) m = fmaxf(m, img[i]);
    #pragma unroll
    for (int o = 16; o; o >>= 1) m = fmaxf(m, __shfl_xor_sync(0xFFFFFFFFu, m, o));
    __shared__ float s[32];
    if ((threadIdx.x & 31) == 0) s[threadIdx.x >> 5] = m;
    __syncthreads();
    if (threadIdx.x < 32) {
        int nw = blockDim.x >> 5;
        m = (threadIdx.x < nw) ? s[threadIdx.x] : 0.0f;
        #pragma unroll
        for (int o = 16; o; o >>= 1) m = fmaxf(m, __shfl_xor_sync(0xFFFFFFFFu, m, o));
        // positive floats: uint bit pattern is order-preserving
        if (threadIdx.x == 0) atomicMax(&g_max_bits[n], __float_as_uint(m));
    }
}

// ---------------------------------------------------------------- peak bitmask
// grid (A, N_IMG), block 384 = 12 warps; warp w covers r in [32w, 32w+32)
__global__ void dm_peak_kernel(const float* __restrict__ in) {
    const int n = blockIdx.y;
    const int a = blockIdx.x;
    const int warp = threadIdx.x >> 5;
    const int lane = threadIdx.x & 31;
    const int r = warp * 32 + lane;
    const float* img = in + (size_t)n * (A * R);
    const float thr = 0.5f * __uint_as_float(g_max_bits[n]);

    bool pk = false;
    if (r < R) {
        float v = img[a * R + r];
        if (v > thr) {
            pk = true;
            #pragma unroll
            for (int da = -1; da <= 1; da++) {
                int aa = a + da;
                if (aa < 0 || aa >= A) continue;
                #pragma unroll
                for (int dr = -1; dr <= 1; dr++) {
                    if (da == 0 && dr == 0) continue;
                    int rr = r + dr;
                    if (rr < 0 || rr >= R) continue;
                    if (img[aa * R + rr] > v) { pk = false; }
                }
            }
        }
    }
    unsigned int word = __ballot_sync(0xFFFFFFFFu, pk);
    if (lane == 0) g_peak[((size_t)n * A + a) * RW + warp] = word;
}

// ---------------------------------------------------------------- pixel mask
// grid (H*W / PIX_PER_BLOCK, N_IMG), block 256
__global__ void dm_mask_kernel(float* __restrict__ out) {
    __shared__ unsigned int s_peak[A * RW];   // 17.28 KB
    __shared__ float s_ct[A];
    __shared__ float s_st[A];

    const int n = blockIdx.y;
    for (int i = threadIdx.x; i < A * RW; i += blockDim.x)
        s_peak[i] = g_peak[(size_t)n * A * RW + i];
    for (int i = threadIdx.x; i < A; i += blockDim.x) {
        float th = (float)i * (float)(M_PI / 360.0);
        s_ct[i] = cosf(th);
        s_st[i] = sinf(th);
    }
    __syncthreads();

    const float delta     = (float)DELTA_RHO_D;
    const float inv_delta = 1.0f / (float)DELTA_RHO_D;
    const int   base      = blockIdx.x * PIX_PER_BLOCK;
    float* oimg = out + (size_t)n * (H * W);

    for (int pp = threadIdx.x; pp < PIX_PER_BLOCK; pp += blockDim.x) {
        int p = base + pp;
        int h = p >> 8;          // p / W, W=256
        int w = p & 255;         // p % W
        float x = (float)w - 127.5f;   // (W-1)/2
        float y = (float)h - 127.5f;   // (H-1)/2
        float res = 0.0f;

        for (int a = 0; a < A; a++) {
            float rho = s_ct[a] * x + s_st[a] * y;
            float rc  = rho * inv_delta + 180.0f;
            int fl = (int)floorf(rc);
            int lo = fl - 3;
            int hi = fl + 3;      // conservative 7-candidate window (3/delta = 2.975)
            if (lo < 0)   lo = 0;
            if (hi > R-1) hi = R - 1;
            if (lo > hi) continue;

            const unsigned int* pw = &s_peak[a * RW];
            int w0 = lo >> 5;
            int w1 = hi >> 5;
            unsigned long long pk64 = (unsigned long long)pw[w0];
            if (w1 != w0) pk64 |= ((unsigned long long)pw[w1]) << 32;
            int s0 = lo - (w0 << 5);
            int s1 = hi - (w0 << 5);   // s1 - s0 <= 6, s1 < 38
            unsigned long long m = (((1ull << (s1 - s0 + 1)) - 1ull) << s0);
            pk64 &= m;

            while (pk64) {
                int b = __ffsll((long long)pk64) - 1;
                pk64 &= pk64 - 1ull;
                int rr = (w0 << 5) + b;
                float rv = (float)(rr - 180) * delta;     // matches reference rho_vals
                if (fabsf(rho - rv) < 3.0f) { res = 1.0f; break; }
            }
            if (res != 0.0f) break;
        }
        oimg[p] = res;
    }
}

// ---------------------------------------------------------------- launch
extern "C" void kernel_launch(void* const* d_in, const int* in_sizes, int n_in,
                              void* d_out, int out_size) {
    const float* in = (const float*)d_in[0];
    float* out = (float*)d_out;

    dm_init_kernel<<<1, 32>>>();
    dm_max_kernel<<<dim3(32, N_IMG), 256>>>(in);
    dm_peak_kernel<<<dim3(A, N_IMG), 384>>>(in);
    dm_mask_kernel<<<dim3((H * W) / PIX_PER_BLOCK, N_IMG), 256>>>(out);
}

// round 2
// speedup vs baseline: 1.1135x; 1.1135x over previous
#include <cuda_runtime.h>
#include <math.h>

#define N_IMG 16
#define A 360
#define R 360
#define H 256
#define W 256
#define RW 12                       // 360 bits -> 12 x 32-bit words per angle
#define PIX_PER_BLOCK 1024
#define MAXB 16                     // blocks per image in max kernel
#define DELTA_RHO_D (2.0 * 181.01933598375618 / 359.0)   // 2*sqrt(128^2+128^2)/359

__device__ float        g_blockmax[N_IMG * MAXB];        // written every run, no init needed
__device__ unsigned int g_peak[N_IMG * A * RW];

// ---------------------------------------------------------------- per-image block max
// grid (MAXB, N_IMG), block 256; float4 loads; plain store per block (no atomics)
__global__ void __launch_bounds__(256) dm_max_kernel(const float* __restrict__ in) {
    const int n = blockIdx.y;
    const float4* img = (const float4*)(in + (size_t)n * (A * R));
    const int nvec = (A * R) / 4;               // 32400
    int tid = blockIdx.x * blockDim.x + threadIdx.x;
    int stride = MAXB * blockDim.x;
    float m = 0.0f;                              // inputs are uniform[0,1): non-negative
    for (int i = tid; i < nvec; i += stride) {
        float4 v = img[i];
        m = fmaxf(m, fmaxf(fmaxf(v.x, v.y), fmaxf(v.z, v.w)));
    }
    #pragma unroll
    for (int o = 16; o; o >>= 1) m = fmaxf(m, __shfl_xor_sync(0xFFFFFFFFu, m, o));
    __shared__ float s[8];
    if ((threadIdx.x & 31) == 0) s[threadIdx.x >> 5] = m;
    __syncthreads();
    if (threadIdx.x < 32) {
        m = (threadIdx.x < 8) ? s[threadIdx.x] : 0.0f;
        #pragma unroll
        for (int o = 4; o; o >>= 1) m = fmaxf(m, __shfl_xor_sync(0xFFFFFFFFu, m, o));
        if (threadIdx.x == 0) g_blockmax[n * MAXB + blockIdx.x] = m;
    }
}

// ---------------------------------------------------------------- peak bitmask
// grid (A, N_IMG), block 384 = 12 warps; warp w covers r in [32w, 32w+32)
__global__ void __launch_bounds__(384) dm_peak_kernel(const float* __restrict__ in) {
    const int n = blockIdx.y;
    const int a = blockIdx.x;
    const int warp = threadIdx.x >> 5;
    const int lane = threadIdx.x & 31;
    const int r = warp * 32 + lane;
    const float* img = in + (size_t)n * (A * R);

    // reduce the 16 per-block maxima for this image (all warps do it; L1-broadcast)
    float bm = (lane < MAXB) ? g_blockmax[n * MAXB + lane] : 0.0f;
    #pragma unroll
    for (int o = 8; o; o >>= 1) bm = fmaxf(bm, __shfl_xor_sync(0xFFFFFFFFu, bm, o));
    const float thr = 0.5f * bm;

    bool pk = false;
    if (r < R) {
        float v = img[a * R + r];
        if (v > thr) {
            pk = true;
            #pragma unroll
            for (int da = -1; da <= 1; da++) {
                int aa = a + da;
                if (aa < 0 || aa >= A) continue;
                #pragma unroll
                for (int dr = -1; dr <= 1; dr++) {
                    if (da == 0 && dr == 0) continue;
                    int rr = r + dr;
                    if (rr < 0 || rr >= R) continue;
                    if (img[aa * R + rr] > v) { pk = false; }
                }
            }
        }
    }
    unsigned int word = __ballot_sync(0xFFFFFFFFu, pk);
    if (lane == 0) g_peak[((size_t)n * A + a) * RW + warp] = word;
}

// ---------------------------------------------------------------- pixel mask
// grid (H*W / PIX_PER_BLOCK, N_IMG), block 256
__global__ void __launch_bounds__(256) dm_mask_kernel(float* __restrict__ out) {
    __shared__ unsigned int s_peak[A * RW];   // 17.28 KB
    __shared__ float s_ct[A];
    __shared__ float s_st[A];

    const int n = blockIdx.y;
    // vectorized peak load: 4320 words = 1080 uint4
    {
        const uint4* src = (const uint4*)&g_peak[(size_t)n * A * RW];
        uint4* dst = (uint4*)s_peak;
        for (int i = threadIdx.x; i < (A * RW) / 4; i += blockDim.x) dst[i] = src[i];
    }
    for (int i = threadIdx.x; i < A; i += blockDim.x) {
        float th = (float)i * (float)(M_PI / 360.0);
        s_ct[i] = cosf(th);
        s_st[i] = sinf(th);
    }
    __syncthreads();

    const float delta     = (float)DELTA_RHO_D;
    const float inv_delta = 1.0f / (float)DELTA_RHO_D;
    const int   base      = blockIdx.x * PIX_PER_BLOCK;
    float* oimg = out + (size_t)n * (H * W);

    for (int pp = threadIdx.x; pp < PIX_PER_BLOCK; pp += blockDim.x) {
        int p = base + pp;
        int h = p >> 8;          // p / W, W=256
        int w = p & 255;         // p % W
        float x = (float)w - 127.5f;   // (W-1)/2
        float y = (float)h - 127.5f;   // (H-1)/2
        float res = 0.0f;

        for (int a = 0; a < A; a++) {
            float rho = s_ct[a] * x + s_st[a] * y;
            float rc  = rho * inv_delta + 180.0f;
            int fl = (int)floorf(rc);
            int lo = fl - 3;
            int hi = fl + 3;      // conservative 7-candidate window (3/delta = 2.975)
            if (lo < 0)   lo = 0;
            if (hi > R-1) hi = R - 1;
            if (lo > hi) continue;

            const unsigned int* pw = &s_peak[a * RW];
            int w0 = lo >> 5;
            int w1 = hi >> 5;
            unsigned long long pk64 = (unsigned long long)pw[w0];
            if (w1 != w0) pk64 |= ((unsigned long long)pw[w1]) << 32;
            int s0 = lo - (w0 << 5);
            int s1 = hi - (w0 << 5);   // s1 - s0 <= 6, s1 < 38
            unsigned long long m = (((1ull << (s1 - s0 + 1)) - 1ull) << s0);
            pk64 &= m;

            while (pk64) {
                int b = __ffsll((long long)pk64) - 1;
                pk64 &= pk64 - 1ull;
                int rr = (w0 << 5) + b;
                float rv = (float)(rr - 180) * delta;     // matches reference rho_vals
                if (fabsf(rho - rv) < 3.0f) { res = 1.0f; break; }
            }
            if (res != 0.0f) break;
        }
        oimg[p] = res;
    }
}

// ---------------------------------------------------------------- launch
extern "C" void kernel_launch(void* const* d_in, const int* in_sizes, int n_in,
                              void* d_out, int out_size) {
    const float* in = (const float*)d_in[0];
    float* out = (float*)d_out;

    dm_max_kernel<<<dim3(MAXB, N_IMG), 256>>>(in);
    dm_peak_kernel<<<dim3(A, N_IMG), 384>>>(in);
    dm_mask_kernel<<<dim3((H * W) / PIX_PER_BLOCK, N_IMG), 256>>>(out);
}

// round 3
// speedup vs baseline: 1.3633x; 1.2243x over previous
#include <cuda_runtime.h>
#include <math.h>

#define N_IMG 16
#define A 360
#define R 360
#define H 256
#define W 256
#define RW 12                       // 360 bits -> 12 x 32-bit words per angle
#define PIX_PER_BLOCK 512
#define MAXB 64                     // blocks per image in max kernel
#define APB 12                      // angles per block in peak kernel
#define DELTA_RHO_D (2.0 * 181.01933598375618 / 359.0)   // 2*sqrt(128^2+128^2)/359

__device__ float        g_blockmax[N_IMG * MAXB];        // written every run, no init needed
__device__ unsigned int g_peak[N_IMG * A * RW];

// ---------------------------------------------------------------- per-image block max
// grid (MAXB, N_IMG), block 256; float4 loads
__global__ void __launch_bounds__(256) dm_max_kernel(const float* __restrict__ in) {
    const int n = blockIdx.y;
    const float4* img = (const float4*)(in + (size_t)n * (A * R));
    const int nvec = (A * R) / 4;               // 32400
    int tid = blockIdx.x * blockDim.x + threadIdx.x;
    int stride = MAXB * 256;                    // 16384
    float m = 0.0f;                              // inputs are uniform[0,1): non-negative
    for (int i = tid; i < nvec; i += stride) {   // ~2 iterations, independent
        float4 v = img[i];
        m = fmaxf(m, fmaxf(fmaxf(v.x, v.y), fmaxf(v.z, v.w)));
    }
    #pragma unroll
    for (int o = 16; o; o >>= 1) m = fmaxf(m, __shfl_xor_sync(0xFFFFFFFFu, m, o));
    __shared__ float s[8];
    if ((threadIdx.x & 31) == 0) s[threadIdx.x >> 5] = m;
    __syncthreads();
    if (threadIdx.x < 32) {
        m = (threadIdx.x < 8) ? s[threadIdx.x] : 0.0f;
        #pragma unroll
        for (int o = 4; o; o >>= 1) m = fmaxf(m, __shfl_xor_sync(0xFFFFFFFFu, m, o));
        if (threadIdx.x == 0) g_blockmax[n * MAXB + blockIdx.x] = m;
    }
}

// ---------------------------------------------------------------- peak bitmask (smem-tiled)
// grid (A/APB, N_IMG), block 384 = 12 warps; warp w handles angle a0+w, all 360 r
__global__ void __launch_bounds__(384) dm_peak_kernel(const float* __restrict__ in) {
    __shared__ float s_rows[(APB + 2) * R];      // 14 x 360 floats = 20.16 KB

    const int n  = blockIdx.y;
    const int a0 = blockIdx.x * APB;
    const int warp = threadIdx.x >> 5;
    const int lane = threadIdx.x & 31;
    const float* img = in + (size_t)n * (A * R);

    // load rows [a0-1 .. a0+APB] into smem; out-of-range angles -> -INF
    for (int idx = threadIdx.x; idx < (APB + 2) * (R / 4); idx += 384) {
        int row = idx / (R / 4);                 // 0..13
        int q   = idx % (R / 4);
        int a   = a0 - 1 + row;
        float4 v;
        if (a >= 0 && a < A) {
            v = ((const float4*)(img + a * R))[q];
        } else {
            v = make_float4(-INFINITY, -INFINITY, -INFINITY, -INFINITY);
        }
        ((float4*)(s_rows + row * R))[q] = v;
    }

    // threshold: reduce 64 per-block maxima for this image
    float bm = fmaxf(g_blockmax[n * MAXB + lane], g_blockmax[n * MAXB + 32 + lane]);
    #pragma unroll
    for (int o = 16; o; o >>= 1) bm = fmaxf(bm, __shfl_xor_sync(0xFFFFFFFFu, bm, o));
    const float thr = 0.5f * bm;

    __syncthreads();

    const int a = a0 + warp;                     // this warp's angle
    const float* rm = s_rows + warp * R;         // a-1 row
    const float* rc = rm + R;                    // a   row
    const float* rp = rc + R;                    // a+1 row
    unsigned int* dst = &g_peak[((size_t)n * A + a) * RW];

    #pragma unroll
    for (int i = 0; i < RW; i++) {
        int r = i * 32 + lane;
        bool pk = false;
        if (r < R) {
            float v = rc[r];
            if (v > thr) {
                pk = true;
                // same-row neighbors
                if (r > 0     && rc[r - 1] > v) pk = false;
                if (r < R - 1 && rc[r + 1] > v) pk = false;
                // adjacent-angle rows (out-of-range rows hold -INF)
                if (rm[r] > v) pk = false;
                if (r > 0     && rm[r - 1] > v) pk = false;
                if (r < R - 1 && rm[r + 1] > v) pk = false;
                if (rp[r] > v) pk = false;
                if (r > 0     && rp[r - 1] > v) pk = false;
                if (r < R - 1 && rp[r + 1] > v) pk = false;
            }
        }
        unsigned int word = __ballot_sync(0xFFFFFFFFu, pk);
        if (lane == 0) dst[i] = word;
    }
}

// ---------------------------------------------------------------- pixel mask
// grid (H*W / PIX_PER_BLOCK, N_IMG), block 256
__global__ void __launch_bounds__(256) dm_mask_kernel(float* __restrict__ out) {
    __shared__ unsigned int s_peak[A * RW];   // 17.28 KB
    __shared__ float s_ct[A];
    __shared__ float s_st[A];

    const int n = blockIdx.y;
    // vectorized peak load: 4320 words = 1080 uint4
    {
        const uint4* src = (const uint4*)&g_peak[(size_t)n * A * RW];
        uint4* dst = (uint4*)s_peak;
        for (int i = threadIdx.x; i < (A * RW) / 4; i += blockDim.x) dst[i] = src[i];
    }
    for (int i = threadIdx.x; i < A; i += blockDim.x) {
        float th = (float)i * (float)(M_PI / 360.0);
        s_ct[i] = cosf(th);
        s_st[i] = sinf(th);
    }
    __syncthreads();

    const float delta     = (float)DELTA_RHO_D;
    const float inv_delta = 1.0f / (float)DELTA_RHO_D;
    const int   base      = blockIdx.x * PIX_PER_BLOCK;
    float* oimg = out + (size_t)n * (H * W);

    for (int pp = threadIdx.x; pp < PIX_PER_BLOCK; pp += blockDim.x) {
        int p = base + pp;
        int h = p >> 8;          // p / W, W=256
        int w = p & 255;         // p % W
        float x = (float)w - 127.5f;   // (W-1)/2
        float y = (float)h - 127.5f;   // (H-1)/2
        float res = 0.0f;

        for (int a = 0; a < A; a++) {
            float rho = s_ct[a] * x + s_st[a] * y;
            float rc  = rho * inv_delta + 180.0f;
            int fl = (int)floorf(rc);
            int lo = fl - 3;
            int hi = fl + 3;      // conservative 7-candidate window (3/delta = 2.975)
            if (lo < 0)   lo = 0;
            if (hi > R-1) hi = R - 1;
            if (lo > hi) continue;

            const unsigned int* pw = &s_peak[a * RW];
            int w0 = lo >> 5;
            int w1 = hi >> 5;
            unsigned long long pk64 = (unsigned long long)pw[w0];
            if (w1 != w0) pk64 |= ((unsigned long long)pw[w1]) << 32;
            int s0 = lo - (w0 << 5);
            int s1 = hi - (w0 << 5);   // s1 - s0 <= 6, s1 < 38
            unsigned long long m = (((1ull << (s1 - s0 + 1)) - 1ull) << s0);
            pk64 &= m;

            while (pk64) {
                int b = __ffsll((long long)pk64) - 1;
                pk64 &= pk64 - 1ull;
                int rr = (w0 << 5) + b;
                float rv = (float)(rr - 180) * delta;     // matches reference rho_vals
                if (fabsf(rho - rv) < 3.0f) { res = 1.0f; break; }
            }
            if (res != 0.0f) break;
        }
        oimg[p] = res;
    }
}

// ---------------------------------------------------------------- launch
extern "C" void kernel_launch(void* const* d_in, const int* in_sizes, int n_in,
                              void* d_out, int out_size) {
    const float* in = (const float*)d_in[0];
    float* out = (float*)d_out;

    dm_max_kernel<<<dim3(MAXB, N_IMG), 256>>>(in);
    dm_peak_kernel<<<dim3(A / APB, N_IMG), 384>>>(in);
    dm_mask_kernel<<<dim3((H * W) / PIX_PER_BLOCK, N_IMG), 256>>>(out);
}